// round 1
// baseline (speedup 1.0000x reference)
#include <cuda_runtime.h>
#include <cstddef>

// Problem constants
constexpr int SEQ  = 1024;
constexpr int HID  = 1024;
constexpr int NH   = 16;
constexpr int HD   = 64;
constexpr int BB   = 4;
constexpr int BH   = BB * NH;      // 64

// Scratch (head-major Q/K/V): [bh][s][d]
__device__ float g_Q[(size_t)BH * SEQ * HD];
__device__ float g_K[(size_t)BH * SEQ * HD];
__device__ float g_V[(size_t)BH * SEQ * HD];

// ---------------------------------------------------------------------------
// Kernel 1: fused QKV projection  C[m,n] = X[m,:]·W[n,:] + bias[n]
// M=4096, N=3072, K=1024.  Scatter into g_Q/g_K/g_V head-major.
// ---------------------------------------------------------------------------
constexpr int BM = 128;
constexpr int BN = 64;
constexpr int BK = 16;

__global__ __launch_bounds__(256)
void qkv_kernel(const float* __restrict__ X, const float* __restrict__ W,
                const float* __restrict__ bias) {
    __shared__ float As[BK][BM + 4];
    __shared__ float Bs[BK][BN + 4];

    const int n0  = blockIdx.x * BN;
    const int m0  = blockIdx.y * BM;
    const int tid = threadIdx.x;
    const int tn  = tid & 15;   // 16 col groups * 4 cols
    const int tm  = tid >> 4;   // 16 row groups * 8 rows

    float acc[8][4];
#pragma unroll
    for (int i = 0; i < 8; i++)
#pragma unroll
        for (int jj = 0; jj < 4; jj++) acc[i][jj] = 0.f;

    for (int k0 = 0; k0 < HID; k0 += BK) {
        // A tile: 128x16 (512 float4, 2 per thread), store transposed
#pragma unroll
        for (int p = 0; p < 2; p++) {
            int idx = tid + p * 256;
            int row = idx >> 2, c4 = idx & 3;
            float4 v = *(const float4*)(X + (size_t)(m0 + row) * HID + k0 + c4 * 4);
            As[c4 * 4 + 0][row] = v.x; As[c4 * 4 + 1][row] = v.y;
            As[c4 * 4 + 2][row] = v.z; As[c4 * 4 + 3][row] = v.w;
        }
        // B tile: 64x16 (256 float4, 1 per thread)
        {
            int row = tid >> 2, c4 = tid & 3;
            float4 v = *(const float4*)(W + (size_t)(n0 + row) * HID + k0 + c4 * 4);
            Bs[c4 * 4 + 0][row] = v.x; Bs[c4 * 4 + 1][row] = v.y;
            Bs[c4 * 4 + 2][row] = v.z; Bs[c4 * 4 + 3][row] = v.w;
        }
        __syncthreads();
#pragma unroll
        for (int k = 0; k < BK; k++) {
            float a[8], bq[4];
#pragma unroll
            for (int i = 0; i < 8; i++) a[i] = As[k][tm * 8 + i];
#pragma unroll
            for (int jj = 0; jj < 4; jj++) bq[jj] = Bs[k][tn * 4 + jj];
#pragma unroll
            for (int i = 0; i < 8; i++)
#pragma unroll
                for (int jj = 0; jj < 4; jj++)
                    acc[i][jj] = fmaf(a[i], bq[jj], acc[i][jj]);
        }
        __syncthreads();
    }

    // Epilogue: whole CTA falls in one part (q/k/v) and one head (BN=64)
    const int part = n0 >> 10;                 // 0=q, 1=k, 2=v
    const int head = (n0 & 1023) >> 6;
    float* dst = (part == 0) ? g_Q : (part == 1) ? g_K : g_V;
    float4 b4 = *(const float4*)(bias + n0 + tn * 4);
#pragma unroll
    for (int i = 0; i < 8; i++) {
        int m = m0 + tm * 8 + i;
        int bidx = m >> 10, s = m & 1023;
        float4 o;
        o.x = acc[i][0] + b4.x; o.y = acc[i][1] + b4.y;
        o.z = acc[i][2] + b4.z; o.w = acc[i][3] + b4.w;
        *(float4*)(dst + (((size_t)(bidx * NH + head) * SEQ + s) * HD) + tn * 4) = o;
    }
}

// ---------------------------------------------------------------------------
// Kernel 2: fused attention with relative_key_query bias, flash-style.
// scores[l,r] = ( q·k + (q+k)·E[l-r+1023] ) / 8 + mask[b,r]
// One CTA = (bh, 64-row l tile); iterate 64-col r tiles.
// Thread map: 256 thr = 64 l-rows x 4 (j).  Scores: r = j + 4*rr (16/thr).
// PV: thread owns d in [j*16, j*16+16).
// ---------------------------------------------------------------------------
constexpr int TL = 64;
constexpr int TR = 64;
constexpr int EP = 68;   // padded row stride (floats)

constexpr size_t SMEM_FLOATS =
    (size_t)TL * EP      // sQ
  + (size_t)TR * EP      // sK
  + (size_t)128 * EP     // sE (127 rows used)
  + (size_t)TR * HD      // sV
  + (size_t)TL * EP      // sP
  + TR;                  // sM
constexpr size_t SMEM_BYTES = SMEM_FLOATS * 4;

__global__ __launch_bounds__(256, 2)
void attn_kernel(const float* __restrict__ E, const float* __restrict__ mask,
                 float* __restrict__ out) {
    extern __shared__ float sm[];
    float* sQ = sm;
    float* sK = sQ + TL * EP;
    float* sE = sK + TR * EP;
    float* sV = sE + 128 * EP;
    float* sP = sV + TR * HD;
    float* sM = sP + TL * EP;

    const int bh   = blockIdx.y;
    const int b    = bh >> 4;
    const int head = bh & 15;
    const int l0   = blockIdx.x * TL;
    const int tid  = threadIdx.x;
    const int l    = tid >> 2;
    const int j    = tid & 3;

    const float* Qg = g_Q + (size_t)bh * SEQ * HD;
    const float* Kg = g_K + (size_t)bh * SEQ * HD;
    const float* Vg = g_V + (size_t)bh * SEQ * HD;

    // Load Q tile once
#pragma unroll
    for (int p = 0; p < 4; p++) {
        int idx = tid + p * 256;                 // 1024 float4
        int row = idx >> 4, c4 = idx & 15;
        *(float4*)(sQ + row * EP + c4 * 4) =
            *(const float4*)(Qg + (size_t)(l0 + row) * HD + c4 * 4);
    }

    float o[16];
#pragma unroll
    for (int i = 0; i < 16; i++) o[i] = 0.f;
    float mrun = -1e30f, lsum = 0.f;

    for (int t = 0; t < SEQ / TR; t++) {
        const int r0 = t * TR;
        __syncthreads();   // previous PV done with sV/sP; loads may overwrite

        // Load K,V tiles
#pragma unroll
        for (int p = 0; p < 4; p++) {
            int idx = tid + p * 256;
            int row = idx >> 4, c4 = idx & 15;
            *(float4*)(sK + row * EP + c4 * 4) =
                *(const float4*)(Kg + (size_t)(r0 + row) * HD + c4 * 4);
            *(float4*)(sV + row * HD + c4 * 4) =
                *(const float4*)(Vg + (size_t)(r0 + row) * HD + c4 * 4);
        }
        // dist_emb window: rows [base, base+127), base = l0-r0+960, w = l-r+63
        const int base = l0 - r0 + 960;
        for (int idx = tid; idx < 127 * 16; idx += 256) {
            int w = idx >> 4, c4 = idx & 15;
            *(float4*)(sE + w * EP + c4 * 4) =
                *(const float4*)(E + (size_t)(base + w) * HD + c4 * 4);
        }
        if (tid < TR) sM[tid] = mask[b * SEQ + r0 + tid];
        __syncthreads();

        // ---- scores: acc[rr] = q[l]·k[r] + (q[l]+k[r])·e[l-r+63],  r=j+4rr
        float accv[16];
#pragma unroll
        for (int rr = 0; rr < 16; rr++) accv[rr] = 0.f;
        const float* qrow   = sQ + l * EP;
        const float* kbase0 = sK + j * EP;
        const float* ebase0 = sE + (l - j + 63) * EP;
#pragma unroll 2
        for (int dc = 0; dc < 16; dc++) {
            float4 q4 = *(const float4*)(qrow + dc * 4);
            const float* kb = kbase0 + dc * 4;
            const float* eb = ebase0 + dc * 4;
#pragma unroll
            for (int rr = 0; rr < 16; rr++) {
                float4 k4 = *(const float4*)(kb + rr * (4 * EP));
                float4 e4 = *(const float4*)(eb - rr * (4 * EP));
                float sv = accv[rr];
                sv = fmaf(q4.x, k4.x, sv); sv = fmaf(q4.x + k4.x, e4.x, sv);
                sv = fmaf(q4.y, k4.y, sv); sv = fmaf(q4.y + k4.y, e4.y, sv);
                sv = fmaf(q4.z, k4.z, sv); sv = fmaf(q4.z + k4.z, e4.z, sv);
                sv = fmaf(q4.w, k4.w, sv); sv = fmaf(q4.w + k4.w, e4.w, sv);
                accv[rr] = sv;
            }
        }

        // ---- online softmax (quad = 4 lanes of one row)
        float mt = -1e30f;
#pragma unroll
        for (int rr = 0; rr < 16; rr++) {
            float sv = accv[rr] * 0.125f + sM[j + 4 * rr];
            accv[rr] = sv;
            mt = fmaxf(mt, sv);
        }
        mt = fmaxf(mt, __shfl_xor_sync(0xffffffffu, mt, 1));
        mt = fmaxf(mt, __shfl_xor_sync(0xffffffffu, mt, 2));
        float mnew = fmaxf(mrun, mt);
        float corr = __expf(mrun - mnew);
        float ps = 0.f;
#pragma unroll
        for (int rr = 0; rr < 16; rr++) {
            float p = __expf(accv[rr] - mnew);
            sP[l * EP + j + 4 * rr] = p;
            ps += p;
        }
        ps += __shfl_xor_sync(0xffffffffu, ps, 1);
        ps += __shfl_xor_sync(0xffffffffu, ps, 2);
        lsum = lsum * corr + ps;
        mrun = mnew;
#pragma unroll
        for (int i = 0; i < 16; i++) o[i] *= corr;
        __syncthreads();

        // ---- PV: o[d] += p[l,r] * V[r,d], d = j*16 + i
        const float4* prow = (const float4*)(sP + l * EP);
#pragma unroll 4
        for (int r4 = 0; r4 < 16; r4++) {
            float4 p4 = prow[r4];
            const float* vb = sV + (r4 * 4) * HD + j * 16;
#pragma unroll
            for (int q = 0; q < 4; q++) {
                float pq = (q == 0) ? p4.x : (q == 1) ? p4.y : (q == 2) ? p4.z : p4.w;
                const float4* vr = (const float4*)(vb + q * HD);
                float4 v0 = vr[0], v1 = vr[1], v2 = vr[2], v3 = vr[3];
                o[0]  = fmaf(pq, v0.x, o[0]);   o[1]  = fmaf(pq, v0.y, o[1]);
                o[2]  = fmaf(pq, v0.z, o[2]);   o[3]  = fmaf(pq, v0.w, o[3]);
                o[4]  = fmaf(pq, v1.x, o[4]);   o[5]  = fmaf(pq, v1.y, o[5]);
                o[6]  = fmaf(pq, v1.z, o[6]);   o[7]  = fmaf(pq, v1.w, o[7]);
                o[8]  = fmaf(pq, v2.x, o[8]);   o[9]  = fmaf(pq, v2.y, o[9]);
                o[10] = fmaf(pq, v2.z, o[10]);  o[11] = fmaf(pq, v2.w, o[11]);
                o[12] = fmaf(pq, v3.x, o[12]);  o[13] = fmaf(pq, v3.y, o[13]);
                o[14] = fmaf(pq, v3.z, o[14]);  o[15] = fmaf(pq, v3.w, o[15]);
            }
        }
    }

    // out[b, s, head*64 + d]
    float inv = 1.f / lsum;
    float* op = out + ((size_t)(b * SEQ + l0 + l) * HID) + head * HD + j * 16;
#pragma unroll
    for (int q = 0; q < 4; q++) {
        float4 vv = make_float4(o[q * 4 + 0] * inv, o[q * 4 + 1] * inv,
                                o[q * 4 + 2] * inv, o[q * 4 + 3] * inv);
        *(float4*)(op + q * 4) = vv;
    }
}

// ---------------------------------------------------------------------------
extern "C" void kernel_launch(void* const* d_in, const int* in_sizes, int n_in,
                              void* d_out, int out_size) {
    const float* X    = (const float*)d_in[0];   // hidden_states [4,1024,1024]
    const float* W    = (const float*)d_in[1];   // qkv_w [3072,1024]
    const float* bias = (const float*)d_in[2];   // qkv_b [3072]
    const float* E    = (const float*)d_in[3];   // dist_emb [2047,64]
    const float* msk  = (const float*)d_in[4];   // ext_mask [4,1,1,1024]
    float* out = (float*)d_out;

    dim3 g1(3 * HID / BN, (BB * SEQ) / BM);      // 48 x 32
    qkv_kernel<<<g1, 256>>>(X, W, bias);

    cudaFuncSetAttribute(attn_kernel,
                         cudaFuncAttributeMaxDynamicSharedMemorySize,
                         (int)SMEM_BYTES);
    dim3 g2(SEQ / TL, BH);                       // 16 x 64
    attn_kernel<<<g2, 256, SMEM_BYTES>>>(E, msk, out);
}

// round 2
// speedup vs baseline: 1.0088x; 1.0088x over previous
#include <cuda_runtime.h>
#include <cstddef>

typedef unsigned long long u64;

// Problem constants
constexpr int SEQ  = 1024;
constexpr int HID  = 1024;
constexpr int NH   = 16;
constexpr int HD   = 64;
constexpr int BB   = 4;
constexpr int BH   = BB * NH;      // 64

// Scratch (head-major Q/K/V): [bh][s][d]
__device__ float g_Q[(size_t)BH * SEQ * HD];
__device__ float g_K[(size_t)BH * SEQ * HD];
__device__ float g_V[(size_t)BH * SEQ * HD];

// ---------------------------------------------------------------------------
// Packed fp32x2 helpers (sm_103a): one instruction = 2 fp32 ops.
// ---------------------------------------------------------------------------
__device__ __forceinline__ u64 ffma2(u64 a, u64 b, u64 c) {
    u64 d;
    asm("fma.rn.f32x2 %0, %1, %2, %3;" : "=l"(d) : "l"(a), "l"(b), "l"(c));
    return d;
}
__device__ __forceinline__ u64 fadd2(u64 a, u64 b) {
    u64 d;
    asm("add.rn.f32x2 %0, %1, %2;" : "=l"(d) : "l"(a), "l"(b));
    return d;
}
__device__ __forceinline__ u64 fmul2(u64 a, u64 b) {
    u64 d;
    asm("mul.rn.f32x2 %0, %1, %2;" : "=l"(d) : "l"(a), "l"(b));
    return d;
}
__device__ __forceinline__ u64 pack2(float lo, float hi) {
    u64 d;
    asm("mov.b64 %0, {%1, %2};" : "=l"(d) : "f"(lo), "f"(hi));
    return d;
}
__device__ __forceinline__ float2 unpack2(u64 v) {
    float lo, hi;
    asm("mov.b64 {%0, %1}, %2;" : "=f"(lo), "=f"(hi) : "l"(v));
    return make_float2(lo, hi);
}

// ---------------------------------------------------------------------------
// Kernel 1: fused QKV projection  C[m,n] = X[m,:]·W[n,:] + bias[n]
// M=4096, N=3072, K=1024.  Scatter into g_Q/g_K/g_V head-major.
// f32x2 mainloop: acc packed over pairs of output rows (i).
// ---------------------------------------------------------------------------
constexpr int BM = 128;
constexpr int BN = 64;
constexpr int BK = 16;

__global__ __launch_bounds__(256)
void qkv_kernel(const float* __restrict__ X, const float* __restrict__ W,
                const float* __restrict__ bias) {
    __shared__ float As[BK][BM + 4];
    __shared__ float Bs[BK][BN + 4];

    const int n0  = blockIdx.x * BN;
    const int m0  = blockIdx.y * BM;
    const int tid = threadIdx.x;
    const int tn  = tid & 15;   // 16 col groups * 4 cols
    const int tm  = tid >> 4;   // 16 row groups * 8 rows

    // acc2[jj][ii] packs output rows (tm*8 + 2*ii, +1) for column tn*4+jj
    u64 acc2[4][4];
#pragma unroll
    for (int jj = 0; jj < 4; jj++)
#pragma unroll
        for (int ii = 0; ii < 4; ii++) acc2[jj][ii] = 0ull;

    for (int k0 = 0; k0 < HID; k0 += BK) {
        // A tile: 128x16 (512 float4, 2 per thread), store transposed
#pragma unroll
        for (int p = 0; p < 2; p++) {
            int idx = tid + p * 256;
            int row = idx >> 2, c4 = idx & 3;
            float4 v = *(const float4*)(X + (size_t)(m0 + row) * HID + k0 + c4 * 4);
            As[c4 * 4 + 0][row] = v.x; As[c4 * 4 + 1][row] = v.y;
            As[c4 * 4 + 2][row] = v.z; As[c4 * 4 + 3][row] = v.w;
        }
        // B tile: 64x16 (256 float4, 1 per thread)
        {
            int row = tid >> 2, c4 = tid & 3;
            float4 v = *(const float4*)(W + (size_t)(n0 + row) * HID + k0 + c4 * 4);
            Bs[c4 * 4 + 0][row] = v.x; Bs[c4 * 4 + 1][row] = v.y;
            Bs[c4 * 4 + 2][row] = v.z; Bs[c4 * 4 + 3][row] = v.w;
        }
        __syncthreads();
#pragma unroll
        for (int k = 0; k < BK; k++) {
            u64 a2[4];
#pragma unroll
            for (int ii = 0; ii < 4; ii++)
                a2[ii] = *(const u64*)(&As[k][tm * 8 + ii * 2]);
            float4 b4 = *(const float4*)(&Bs[k][tn * 4]);
            u64 bb[4];
            bb[0] = pack2(b4.x, b4.x); bb[1] = pack2(b4.y, b4.y);
            bb[2] = pack2(b4.z, b4.z); bb[3] = pack2(b4.w, b4.w);
#pragma unroll
            for (int jj = 0; jj < 4; jj++)
#pragma unroll
                for (int ii = 0; ii < 4; ii++)
                    acc2[jj][ii] = ffma2(a2[ii], bb[jj], acc2[jj][ii]);
        }
        __syncthreads();
    }

    // Epilogue: whole CTA falls in one part (q/k/v) and one head (BN=64)
    const int part = n0 >> 10;                 // 0=q, 1=k, 2=v
    const int head = (n0 & 1023) >> 6;
    float* dst = (part == 0) ? g_Q : (part == 1) ? g_K : g_V;
    float4 b4 = *(const float4*)(bias + n0 + tn * 4);
#pragma unroll
    for (int ii = 0; ii < 4; ii++) {
        float2 c0 = unpack2(acc2[0][ii]);
        float2 c1 = unpack2(acc2[1][ii]);
        float2 c2 = unpack2(acc2[2][ii]);
        float2 c3 = unpack2(acc2[3][ii]);
#pragma unroll
        for (int h = 0; h < 2; h++) {
            int i = ii * 2 + h;
            int m = m0 + tm * 8 + i;
            int bidx = m >> 10, s = m & 1023;
            float4 o;
            o.x = (h ? c0.y : c0.x) + b4.x;
            o.y = (h ? c1.y : c1.x) + b4.y;
            o.z = (h ? c2.y : c2.x) + b4.z;
            o.w = (h ? c3.y : c3.x) + b4.w;
            *(float4*)(dst + (((size_t)(bidx * NH + head) * SEQ + s) * HD) + tn * 4) = o;
        }
    }
}

// ---------------------------------------------------------------------------
// Kernel 2: fused attention with relative_key_query bias, flash-style.
// scores[l,r] = ( q·k + (q+k)·E[l-r+1023] ) / 8 + mask[b,r]
// One CTA = (bh, 64-row l tile); iterate 64-col r tiles.
// Thread map: 256 thr = 64 l-rows x 4 (j).  Scores: r = j + 4*rr (16/thr).
// PV: thread owns d in [j*16, j*16+16).
// f32x2 everywhere in the hot loops.
// ---------------------------------------------------------------------------
constexpr int TL = 64;
constexpr int TR = 64;
constexpr int EP = 68;   // padded row stride (floats)

constexpr size_t SMEM_FLOATS =
    (size_t)TL * EP      // sQ
  + (size_t)TR * EP      // sK
  + (size_t)128 * EP     // sE (127 rows used)
  + (size_t)TR * HD      // sV
  + (size_t)TL * EP      // sP
  + TR;                  // sM
constexpr size_t SMEM_BYTES = SMEM_FLOATS * 4;

__global__ __launch_bounds__(256, 2)
void attn_kernel(const float* __restrict__ E, const float* __restrict__ mask,
                 float* __restrict__ out) {
    extern __shared__ float sm[];
    float* sQ = sm;
    float* sK = sQ + TL * EP;
    float* sE = sK + TR * EP;
    float* sV = sE + 128 * EP;
    float* sP = sV + TR * HD;
    float* sM = sP + TL * EP;

    const int bh   = blockIdx.y;
    const int b    = bh >> 4;
    const int head = bh & 15;
    const int l0   = blockIdx.x * TL;
    const int tid  = threadIdx.x;
    const int l    = tid >> 2;
    const int j    = tid & 3;

    const float* Qg = g_Q + (size_t)bh * SEQ * HD;
    const float* Kg = g_K + (size_t)bh * SEQ * HD;
    const float* Vg = g_V + (size_t)bh * SEQ * HD;

    // Load Q tile once
#pragma unroll
    for (int p = 0; p < 4; p++) {
        int idx = tid + p * 256;                 // 1024 float4
        int row = idx >> 4, c4 = idx & 15;
        *(float4*)(sQ + row * EP + c4 * 4) =
            *(const float4*)(Qg + (size_t)(l0 + row) * HD + c4 * 4);
    }

    u64 o2[8];
#pragma unroll
    for (int i = 0; i < 8; i++) o2[i] = 0ull;
    float mrun = -1e30f, lsum = 0.f;

    for (int t = 0; t < SEQ / TR; t++) {
        const int r0 = t * TR;
        __syncthreads();   // previous PV done with sV/sP; loads may overwrite

        // Load K,V tiles
#pragma unroll
        for (int p = 0; p < 4; p++) {
            int idx = tid + p * 256;
            int row = idx >> 4, c4 = idx & 15;
            *(float4*)(sK + row * EP + c4 * 4) =
                *(const float4*)(Kg + (size_t)(r0 + row) * HD + c4 * 4);
            *(float4*)(sV + row * HD + c4 * 4) =
                *(const float4*)(Vg + (size_t)(r0 + row) * HD + c4 * 4);
        }
        // dist_emb window: rows [base, base+127), base = l0-r0+960, w = l-r+63
        const int base = l0 - r0 + 960;
        for (int idx = tid; idx < 127 * 16; idx += 256) {
            int w = idx >> 4, c4 = idx & 15;
            *(float4*)(sE + w * EP + c4 * 4) =
                *(const float4*)(E + (size_t)(base + w) * HD + c4 * 4);
        }
        if (tid < TR) sM[tid] = mask[b * SEQ + r0 + tid];
        __syncthreads();

        // ---- scores: acc[rr] = q[l]·k[r] + (q[l]+k[r])·e[l-r+63],  r=j+4rr
        u64 acc2[16];
#pragma unroll
        for (int rr = 0; rr < 16; rr++) acc2[rr] = 0ull;
        const float* qrow   = sQ + l * EP;
        const float* kbase0 = sK + j * EP;
        const float* ebase0 = sE + (l - j + 63) * EP;
#pragma unroll 2
        for (int dc = 0; dc < 16; dc++) {
            ulonglong2 q2 = *(const ulonglong2*)(qrow + dc * 4);
            const float* kb = kbase0 + dc * 4;
            const float* eb = ebase0 + dc * 4;
#pragma unroll
            for (int rr = 0; rr < 16; rr++) {
                ulonglong2 k2 = *(const ulonglong2*)(kb + rr * (4 * EP));
                ulonglong2 e2 = *(const ulonglong2*)(eb - rr * (4 * EP));
                u64 sv = acc2[rr];
                sv = ffma2(q2.x, k2.x, sv);
                sv = ffma2(fadd2(q2.x, k2.x), e2.x, sv);
                sv = ffma2(q2.y, k2.y, sv);
                sv = ffma2(fadd2(q2.y, k2.y), e2.y, sv);
                acc2[rr] = sv;
            }
        }

        // ---- online softmax (quad = 4 lanes of one row)
        float accv[16];
        float mt = -1e30f;
#pragma unroll
        for (int rr = 0; rr < 16; rr++) {
            float2 p = unpack2(acc2[rr]);
            float sv = (p.x + p.y) * 0.125f + sM[j + 4 * rr];
            accv[rr] = sv;
            mt = fmaxf(mt, sv);
        }
        mt = fmaxf(mt, __shfl_xor_sync(0xffffffffu, mt, 1));
        mt = fmaxf(mt, __shfl_xor_sync(0xffffffffu, mt, 2));
        float mnew = fmaxf(mrun, mt);
        float corr = __expf(mrun - mnew);
        float ps = 0.f;
#pragma unroll
        for (int rr = 0; rr < 16; rr++) {
            float p = __expf(accv[rr] - mnew);
            sP[l * EP + j + 4 * rr] = p;
            ps += p;
        }
        ps += __shfl_xor_sync(0xffffffffu, ps, 1);
        ps += __shfl_xor_sync(0xffffffffu, ps, 2);
        lsum = lsum * corr + ps;
        mrun = mnew;
        {
            u64 corr2 = pack2(corr, corr);
#pragma unroll
            for (int i = 0; i < 8; i++) o2[i] = fmul2(o2[i], corr2);
        }
        __syncthreads();

        // ---- PV: o[d] += p[l,r] * V[r,d], d = j*16 + {0..15}
        const float4* prow = (const float4*)(sP + l * EP);
#pragma unroll 4
        for (int r4 = 0; r4 < 16; r4++) {
            float4 p4 = prow[r4];
            const float* vb = sV + (r4 * 4) * HD + j * 16;
#pragma unroll
            for (int q = 0; q < 4; q++) {
                float pq = (q == 0) ? p4.x : (q == 1) ? p4.y : (q == 2) ? p4.z : p4.w;
                u64 pq2 = pack2(pq, pq);
                const ulonglong2* vr = (const ulonglong2*)(vb + q * HD);
                ulonglong2 va = vr[0], vbb = vr[1], vc = vr[2], vd = vr[3];
                o2[0] = ffma2(pq2, va.x,  o2[0]);
                o2[1] = ffma2(pq2, va.y,  o2[1]);
                o2[2] = ffma2(pq2, vbb.x, o2[2]);
                o2[3] = ffma2(pq2, vbb.y, o2[3]);
                o2[4] = ffma2(pq2, vc.x,  o2[4]);
                o2[5] = ffma2(pq2, vc.y,  o2[5]);
                o2[6] = ffma2(pq2, vd.x,  o2[6]);
                o2[7] = ffma2(pq2, vd.y,  o2[7]);
            }
        }
    }

    // out[b, s, head*64 + d]
    float inv = 1.f / lsum;
    float* op = out + ((size_t)(b * SEQ + l0 + l) * HID) + head * HD + j * 16;
#pragma unroll
    for (int q = 0; q < 4; q++) {
        float2 lohi0 = unpack2(o2[q * 2 + 0]);
        float2 lohi1 = unpack2(o2[q * 2 + 1]);
        float4 vv = make_float4(lohi0.x * inv, lohi0.y * inv,
                                lohi1.x * inv, lohi1.y * inv);
        *(float4*)(op + q * 4) = vv;
    }
}

// ---------------------------------------------------------------------------
extern "C" void kernel_launch(void* const* d_in, const int* in_sizes, int n_in,
                              void* d_out, int out_size) {
    const float* X    = (const float*)d_in[0];   // hidden_states [4,1024,1024]
    const float* W    = (const float*)d_in[1];   // qkv_w [3072,1024]
    const float* bias = (const float*)d_in[2];   // qkv_b [3072]
    const float* E    = (const float*)d_in[3];   // dist_emb [2047,64]
    const float* msk  = (const float*)d_in[4];   // ext_mask [4,1,1,1024]
    float* out = (float*)d_out;

    dim3 g1(3 * HID / BN, (BB * SEQ) / BM);      // 48 x 32
    qkv_kernel<<<g1, 256>>>(X, W, bias);

    cudaFuncSetAttribute(attn_kernel,
                         cudaFuncAttributeMaxDynamicSharedMemorySize,
                         (int)SMEM_BYTES);
    dim3 g2(SEQ / TL, BH);                       // 16 x 64
    attn_kernel<<<g2, 256, SMEM_BYTES>>>(E, msk, out);
}

// round 4
// speedup vs baseline: 1.1835x; 1.1732x over previous
#include <cuda_runtime.h>
#include <cstddef>

typedef unsigned long long u64;

// Problem constants
constexpr int SEQ  = 1024;
constexpr int HID  = 1024;
constexpr int NH   = 16;
constexpr int HD   = 64;
constexpr int BB   = 4;
constexpr int BH   = BB * NH;      // 64

// Scratch (head-major Q/K/V): [bh][s][d]
__device__ float g_Q[(size_t)BH * SEQ * HD];
__device__ float g_K[(size_t)BH * SEQ * HD];
__device__ float g_V[(size_t)BH * SEQ * HD];

// ---------------------------------------------------------------------------
// Packed fp32x2 helpers (sm_103a)
// ---------------------------------------------------------------------------
__device__ __forceinline__ u64 ffma2(u64 a, u64 b, u64 c) {
    u64 d;
    asm("fma.rn.f32x2 %0, %1, %2, %3;" : "=l"(d) : "l"(a), "l"(b), "l"(c));
    return d;
}
__device__ __forceinline__ u64 fadd2(u64 a, u64 b) {
    u64 d;
    asm("add.rn.f32x2 %0, %1, %2;" : "=l"(d) : "l"(a), "l"(b));
    return d;
}
__device__ __forceinline__ u64 fmul2(u64 a, u64 b) {
    u64 d;
    asm("mul.rn.f32x2 %0, %1, %2;" : "=l"(d) : "l"(a), "l"(b));
    return d;
}
__device__ __forceinline__ u64 pack2(float lo, float hi) {
    u64 d;
    asm("mov.b64 %0, {%1, %2};" : "=l"(d) : "f"(lo), "f"(hi));
    return d;
}
__device__ __forceinline__ float2 unpack2(u64 v) {
    float lo, hi;
    asm("mov.b64 {%0, %1}, %2;" : "=f"(lo), "=f"(hi) : "l"(v));
    return make_float2(lo, hi);
}

// ---------------------------------------------------------------------------
// Kernel 1: fused QKV projection (unchanged; ~78% of fp32 roofline)
// ---------------------------------------------------------------------------
constexpr int BM = 128;
constexpr int BN = 64;
constexpr int BK = 16;

__global__ __launch_bounds__(256)
void qkv_kernel(const float* __restrict__ X, const float* __restrict__ W,
                const float* __restrict__ bias) {
    __shared__ float As[BK][BM + 4];
    __shared__ float Bs[BK][BN + 4];

    const int n0  = blockIdx.x * BN;
    const int m0  = blockIdx.y * BM;
    const int tid = threadIdx.x;
    const int tn  = tid & 15;
    const int tm  = tid >> 4;

    u64 acc2[4][4];
#pragma unroll
    for (int jj = 0; jj < 4; jj++)
#pragma unroll
        for (int ii = 0; ii < 4; ii++) acc2[jj][ii] = 0ull;

    for (int k0 = 0; k0 < HID; k0 += BK) {
#pragma unroll
        for (int p = 0; p < 2; p++) {
            int idx = tid + p * 256;
            int row = idx >> 2, c4 = idx & 3;
            float4 v = *(const float4*)(X + (size_t)(m0 + row) * HID + k0 + c4 * 4);
            As[c4 * 4 + 0][row] = v.x; As[c4 * 4 + 1][row] = v.y;
            As[c4 * 4 + 2][row] = v.z; As[c4 * 4 + 3][row] = v.w;
        }
        {
            int row = tid >> 2, c4 = tid & 3;
            float4 v = *(const float4*)(W + (size_t)(n0 + row) * HID + k0 + c4 * 4);
            Bs[c4 * 4 + 0][row] = v.x; Bs[c4 * 4 + 1][row] = v.y;
            Bs[c4 * 4 + 2][row] = v.z; Bs[c4 * 4 + 3][row] = v.w;
        }
        __syncthreads();
#pragma unroll
        for (int k = 0; k < BK; k++) {
            u64 a2[4];
#pragma unroll
            for (int ii = 0; ii < 4; ii++)
                a2[ii] = *(const u64*)(&As[k][tm * 8 + ii * 2]);
            float4 b4 = *(const float4*)(&Bs[k][tn * 4]);
            u64 bb[4];
            bb[0] = pack2(b4.x, b4.x); bb[1] = pack2(b4.y, b4.y);
            bb[2] = pack2(b4.z, b4.z); bb[3] = pack2(b4.w, b4.w);
#pragma unroll
            for (int jj = 0; jj < 4; jj++)
#pragma unroll
                for (int ii = 0; ii < 4; ii++)
                    acc2[jj][ii] = ffma2(a2[ii], bb[jj], acc2[jj][ii]);
        }
        __syncthreads();
    }

    const int part = n0 >> 10;
    const int head = (n0 & 1023) >> 6;
    float* dst = (part == 0) ? g_Q : (part == 1) ? g_K : g_V;
    float4 b4 = *(const float4*)(bias + n0 + tn * 4);
#pragma unroll
    for (int ii = 0; ii < 4; ii++) {
        float2 c0 = unpack2(acc2[0][ii]);
        float2 c1 = unpack2(acc2[1][ii]);
        float2 c2 = unpack2(acc2[2][ii]);
        float2 c3 = unpack2(acc2[3][ii]);
#pragma unroll
        for (int h = 0; h < 2; h++) {
            int i = ii * 2 + h;
            int m = m0 + tm * 8 + i;
            int bidx = m >> 10, s = m & 1023;
            float4 o;
            o.x = (h ? c0.y : c0.x) + b4.x;
            o.y = (h ? c1.y : c1.x) + b4.y;
            o.z = (h ? c2.y : c2.x) + b4.z;
            o.w = (h ? c3.y : c3.x) + b4.w;
            *(float4*)(dst + (((size_t)(bidx * NH + head) * SEQ + s) * HD) + tn * 4) = o;
        }
    }
}

// ---------------------------------------------------------------------------
// Kernel 2: fused attention, 4x4 register-tiled score GEMM + XOR-swizzled smem
// scores[l,r] = ( q·k + (q+k)·E[l-r+1023] ) / 8 + mask[b,r]
// Score phase:  256 thr = 16 lg x 16 rg, each thread 4l x 4r outputs.
// PV phase:     256 thr = 64 l x 4 j, each thread 1l x 16d.
// Q/K/E stored swizzled: chunk c of row R lives at chunk (c ^ ((R>>2)&15)).
// ---------------------------------------------------------------------------
constexpr int TL  = 64;
constexpr int TR  = 64;
constexpr int EPP = 68;  // sP row stride

constexpr size_t SMEM_FLOATS =
    (size_t)64 * 64      // sQ (swizzled)
  + (size_t)64 * 64      // sK (swizzled)
  + (size_t)128 * 64     // sE (swizzled, 127 rows used)
  + (size_t)64 * 64      // sV (plain)
  + (size_t)64 * EPP     // sP
  + 64                   // sM (mask)
  + 64;                  // sC (corr / inv-lsum handoff)
constexpr size_t SMEM_BYTES = SMEM_FLOATS * 4;

__device__ __forceinline__ int swz(int row, int chunk) {
    // float offset of 16B chunk `chunk` of row `row` (64-float rows)
    return row * 64 + (((chunk ^ (row >> 2)) & 15) << 2);
}

__global__ __launch_bounds__(256, 2)
void attn_kernel(const float* __restrict__ E, const float* __restrict__ mask,
                 float* __restrict__ out) {
    extern __shared__ float sm[];
    float* sQ = sm;
    float* sK = sQ + 64 * 64;
    float* sE = sK + 64 * 64;
    float* sV = sE + 128 * 64;
    float* sP = sV + 64 * 64;
    float* sM = sP + 64 * EPP;
    float* sC = sM + 64;

    const int bh   = blockIdx.y;
    const int b    = bh >> 4;
    const int head = bh & 15;
    const int l0   = blockIdx.x * TL;
    const int tid  = threadIdx.x;
    // score-phase mapping
    const int lg = tid >> 4;
    const int rg = tid & 15;
    const int diag4 = 4 * (lg - rg);
    // PV-phase mapping
    const int lp = tid >> 2;
    const int j  = tid & 3;

    const float* Qg = g_Q + (size_t)bh * SEQ * HD;
    const float* Kg = g_K + (size_t)bh * SEQ * HD;
    const float* Vg = g_V + (size_t)bh * SEQ * HD;

    // Load Q tile once (swizzled)
#pragma unroll
    for (int p = 0; p < 4; p++) {
        int idx = tid + p * 256;
        int row = idx >> 4, c = idx & 15;
        *(float4*)(sQ + swz(row, c)) =
            *(const float4*)(Qg + (size_t)(l0 + row) * HD + c * 4);
    }

    u64 o2[8];
#pragma unroll
    for (int i = 0; i < 8; i++) o2[i] = 0ull;
    float mrun[4], lsum[4];
#pragma unroll
    for (int i = 0; i < 4; i++) { mrun[i] = -1e30f; lsum[i] = 0.f; }

    for (int t = 0; t < SEQ / TR; t++) {
        const int r0 = t * TR;
        __syncthreads();   // prev PV done with sP/sV/sC before refill

        // Fill K (swizzled), V (plain)
#pragma unroll
        for (int p = 0; p < 4; p++) {
            int idx = tid + p * 256;
            int row = idx >> 4, c = idx & 15;
            *(float4*)(sK + swz(row, c)) =
                *(const float4*)(Kg + (size_t)(r0 + row) * HD + c * 4);
            *(float4*)(sV + row * 64 + c * 4) =
                *(const float4*)(Vg + (size_t)(r0 + row) * HD + c * 4);
        }
        // Fill E window (swizzled): local row w = (l-r) - (l0-r0) + 63 in [0,127)
        const int base = l0 - r0 + 960;
        for (int idx = tid; idx < 127 * 16; idx += 256) {
            int w = idx >> 4, c = idx & 15;
            *(float4*)(sE + swz(w, c)) =
                *(const float4*)(E + (size_t)(base + w) * HD + c * 4);
        }
        if (tid < TR) sM[tid] = mask[b * SEQ + r0 + tid];
        __syncthreads();

        // ---- score GEMM: acc2[il][ir] over d (f32x2 partial pairs)
        u64 acc2[4][4];
#pragma unroll
        for (int il = 0; il < 4; il++)
#pragma unroll
            for (int ir = 0; ir < 4; ir++) acc2[il][ir] = 0ull;

#pragma unroll 1
        for (int dc = 0; dc < 16; dc++) {
            const int qoff = (((dc ^ lg) & 15) << 2);
            const int koff = (((dc ^ rg) & 15) << 2);
            u64 qv[4][2], kv[4][2];
#pragma unroll
            for (int il = 0; il < 4; il++) {
                ulonglong2 v = *(const ulonglong2*)(sQ + (4 * lg + il) * 64 + qoff);
                qv[il][0] = v.x; qv[il][1] = v.y;
            }
#pragma unroll
            for (int ir = 0; ir < 4; ir++) {
                ulonglong2 v = *(const ulonglong2*)(sK + (4 * rg + ir) * 64 + koff);
                kv[ir][0] = v.x; kv[ir][1] = v.y;
            }
#pragma unroll
            for (int il = 0; il < 4; il++)
#pragma unroll
                for (int ir = 0; ir < 4; ir++) {
                    acc2[il][ir] = ffma2(qv[il][0], kv[ir][0], acc2[il][ir]);
                    acc2[il][ir] = ffma2(qv[il][1], kv[ir][1], acc2[il][ir]);
                }
            // positional term by diagonal: row R = diag4 + dlt + 63 in [0,126]
#pragma unroll
            for (int dlt = -3; dlt <= 3; dlt++) {
                int R = diag4 + dlt + 63;
                ulonglong2 e2 = *(const ulonglong2*)(
                    sE + R * 64 + ((((dc ^ (R >> 2)) & 15)) << 2));
#pragma unroll
                for (int il = 0; il < 4; il++) {
                    int ir = il - dlt;
                    if (ir >= 0 && ir < 4) {
                        u64 s0 = fadd2(qv[il][0], kv[ir][0]);
                        u64 s1 = fadd2(qv[il][1], kv[ir][1]);
                        acc2[il][ir] = ffma2(s0, e2.x, acc2[il][ir]);
                        acc2[il][ir] = ffma2(s1, e2.y, acc2[il][ir]);
                    }
                }
            }
        }

        // ---- online softmax; rows of this thread: l = 4*lg + il
        float4 mk = *(const float4*)(sM + 4 * rg);
        float corr[4];
#pragma unroll
        for (int il = 0; il < 4; il++) {
            float s[4];
            float mt = -1e30f;
#pragma unroll
            for (int ir = 0; ir < 4; ir++) {
                float2 h = unpack2(acc2[il][ir]);
                float msk = (ir == 0) ? mk.x : (ir == 1) ? mk.y : (ir == 2) ? mk.z : mk.w;
                s[ir] = (h.x + h.y) * 0.125f + msk;
                mt = fmaxf(mt, s[ir]);
            }
            mt = fmaxf(mt, __shfl_xor_sync(0xffffffffu, mt, 1));
            mt = fmaxf(mt, __shfl_xor_sync(0xffffffffu, mt, 2));
            mt = fmaxf(mt, __shfl_xor_sync(0xffffffffu, mt, 4));
            mt = fmaxf(mt, __shfl_xor_sync(0xffffffffu, mt, 8));
            float mnew = fmaxf(mrun[il], mt);
            corr[il] = __expf(mrun[il] - mnew);
            float4 pv;
            pv.x = __expf(s[0] - mnew);
            pv.y = __expf(s[1] - mnew);
            pv.z = __expf(s[2] - mnew);
            pv.w = __expf(s[3] - mnew);
            *(float4*)(sP + (4 * lg + il) * EPP + 4 * rg) = pv;
            float ps = pv.x + pv.y + pv.z + pv.w;
            ps += __shfl_xor_sync(0xffffffffu, ps, 1);
            ps += __shfl_xor_sync(0xffffffffu, ps, 2);
            ps += __shfl_xor_sync(0xffffffffu, ps, 4);
            ps += __shfl_xor_sync(0xffffffffu, ps, 8);
            lsum[il] = lsum[il] * corr[il] + ps;
            mrun[il] = mnew;
        }
        if (rg == 0) {
#pragma unroll
            for (int il = 0; il < 4; il++) sC[4 * lg + il] = corr[il];
        }
        __syncthreads();

        // ---- PV: (lp, j) layout; o[d] += p[lp,r] * V[r,d], d = j*16 + {0..15}
        {
            float cv = sC[lp];
            u64 c2 = pack2(cv, cv);
#pragma unroll
            for (int i = 0; i < 8; i++) o2[i] = fmul2(o2[i], c2);
        }
        const float4* prow = (const float4*)(sP + lp * EPP);
#pragma unroll 4
        for (int r4 = 0; r4 < 16; r4++) {
            float4 p4 = prow[r4];
            const float* vb = sV + (r4 * 4) * 64 + j * 16;
#pragma unroll
            for (int q = 0; q < 4; q++) {
                float pq = (q == 0) ? p4.x : (q == 1) ? p4.y : (q == 2) ? p4.z : p4.w;
                u64 pq2 = pack2(pq, pq);
                const ulonglong2* vr = (const ulonglong2*)(vb + q * 64);
                ulonglong2 va = vr[0], vbb = vr[1], vc = vr[2], vd = vr[3];
                o2[0] = ffma2(pq2, va.x,  o2[0]);
                o2[1] = ffma2(pq2, va.y,  o2[1]);
                o2[2] = ffma2(pq2, vbb.x, o2[2]);
                o2[3] = ffma2(pq2, vbb.y, o2[3]);
                o2[4] = ffma2(pq2, vc.x,  o2[4]);
                o2[5] = ffma2(pq2, vc.y,  o2[5]);
                o2[6] = ffma2(pq2, vd.x,  o2[6]);
                o2[7] = ffma2(pq2, vd.y,  o2[7]);
            }
        }
    }

    // hand 1/lsum over to PV layout
    __syncthreads();
    if (rg == 0) {
#pragma unroll
        for (int il = 0; il < 4; il++) sC[4 * lg + il] = 1.f / lsum[il];
    }
    __syncthreads();
    float inv = sC[lp];

    float* op = out + ((size_t)(b * SEQ + l0 + lp) * HID) + head * HD + j * 16;
#pragma unroll
    for (int q = 0; q < 4; q++) {
        float2 lohi0 = unpack2(o2[q * 2 + 0]);
        float2 lohi1 = unpack2(o2[q * 2 + 1]);
        float4 vv = make_float4(lohi0.x * inv, lohi0.y * inv,
                                lohi1.x * inv, lohi1.y * inv);
        *(float4*)(op + q * 4) = vv;
    }
}

// ---------------------------------------------------------------------------
extern "C" void kernel_launch(void* const* d_in, const int* in_sizes, int n_in,
                              void* d_out, int out_size) {
    const float* X    = (const float*)d_in[0];   // hidden_states [4,1024,1024]
    const float* W    = (const float*)d_in[1];   // qkv_w [3072,1024]
    const float* bias = (const float*)d_in[2];   // qkv_b [3072]
    const float* E    = (const float*)d_in[3];   // dist_emb [2047,64]
    const float* msk  = (const float*)d_in[4];   // ext_mask [4,1,1,1024]
    float* out = (float*)d_out;

    dim3 g1(3 * HID / BN, (BB * SEQ) / BM);      // 48 x 32
    qkv_kernel<<<g1, 256>>>(X, W, bias);

    cudaFuncSetAttribute(attn_kernel,
                         cudaFuncAttributeMaxDynamicSharedMemorySize,
                         (int)SMEM_BYTES);
    dim3 g2(SEQ / TL, BH);                       // 16 x 64
    attn_kernel<<<g2, 256, SMEM_BYTES>>>(E, msk, out);
}